// round 1
// baseline (speedup 1.0000x reference)
#include <cuda_runtime.h>
#include <math.h>

#define NN 8
#define CC 128
#define HH 96
#define WW 96
#define GG 8
#define GCH 16
#define HWSZ (HH*WW)            // 9216
#define NHW (NN*HWSZ)           // 73728
#define OMD 216
#define GN_EPS 1e-5f

// ---------------- device scratch ----------------
__device__ float g_x1[NHW * CC];      // dwconv+bias output, NHWC
__device__ float g_xnhwc[NHW * CC];   // input transposed to NHWC
__device__ float g_om[NHW * OMD];     // offsets/masks GEMM output
__device__ float g_sum[NN];
__device__ float g_sumsq[NN];
__device__ float g_mean[NN];
__device__ float g_rs[NN];

// ---------------- K0: init stats ----------------
__global__ void k_init() {
    int i = threadIdx.x;
    if (i < NN) { g_sum[i] = 0.f; g_sumsq[i] = 0.f; }
}

// ---------------- K1: depthwise conv + bias, NHWC transpose, stats ----------------
// grid (H, C/32, N), block (96, 2)
__global__ __launch_bounds__(192) void k_dwconv(const float* __restrict__ x,
                                                const float* __restrict__ dw_w,
                                                const float* __restrict__ dw_b) {
    int h  = blockIdx.x;
    int cb = blockIdx.y;
    int n  = blockIdx.z;
    int w  = threadIdx.x;
    int ty = threadIdx.y;
    int tid = ty * 96 + w;

    __shared__ float s_out[32][97];
    __shared__ float s_in[32][97];
    __shared__ float rbuf[12];

    float s1 = 0.f, s2 = 0.f;

    #pragma unroll 4
    for (int i = 0; i < 16; ++i) {
        int c = cb * 32 + ty * 16 + i;
        const float* xc = x + ((size_t)(n * CC + c)) * HWSZ;
        float wgt[9];
        #pragma unroll
        for (int t = 0; t < 9; ++t) wgt[t] = dw_w[c * 9 + t];
        float acc = dw_b[c];
        float ctr = 0.f;
        #pragma unroll
        for (int dy = -1; dy <= 1; ++dy) {
            int y = h + dy;
            if ((unsigned)y < HH) {
                #pragma unroll
                for (int dx = -1; dx <= 1; ++dx) {
                    int xx = w + dx;
                    if ((unsigned)xx < WW) {
                        float v = xc[y * WW + xx];
                        acc += v * wgt[(dy + 1) * 3 + (dx + 1)];
                        if (dy == 0 && dx == 0) ctr = v;
                    }
                }
            }
        }
        s_out[ty * 16 + i][w] = acc;
        s_in [ty * 16 + i][w] = ctr;
        s1 += acc;
        s2 += acc * acc;
    }

    // warp reduce
    #pragma unroll
    for (int o = 16; o; o >>= 1) {
        s1 += __shfl_down_sync(0xffffffffu, s1, o);
        s2 += __shfl_down_sync(0xffffffffu, s2, o);
    }
    int wid = tid >> 5, lane = tid & 31;
    if (lane == 0) { rbuf[wid] = s1; rbuf[6 + wid] = s2; }
    __syncthreads();
    if (tid == 0) {
        float a = 0.f, b = 0.f;
        #pragma unroll
        for (int i = 0; i < 6; ++i) { a += rbuf[i]; b += rbuf[6 + i]; }
        atomicAdd(&g_sum[n], a);
        atomicAdd(&g_sumsq[n], b);
    }

    // coalesced NHWC writeout: 32 channels x 96 w
    size_t base = ((size_t)(n * HWSZ + h * WW)) * CC + cb * 32;
    for (int idx = tid; idx < 3072; idx += 192) {
        int ww = idx >> 5;
        int cc = idx & 31;
        g_x1  [base + (size_t)ww * CC + cc] = s_out[cc][ww];
        g_xnhwc[base + (size_t)ww * CC + cc] = s_in[cc][ww];
    }
}

// ---------------- K2: finalize stats ----------------
__global__ void k_stats() {
    int i = threadIdx.x;
    if (i < NN) {
        const float inv = 1.f / (float)(CC * HWSZ);
        float mu  = g_sum[i] * inv;
        float var = g_sumsq[i] * inv - mu * mu;
        g_mean[i] = mu;
        g_rs[i]   = rsqrtf(var + GN_EPS);
    }
}

// ---------------- K3: fused norm+GELU + GEMM (M=73728, N=216, K=128) ----------------
// grid (576, 3), block 256. BM=128, BN=72, BK=16. Thread tile 4x9.
__global__ __launch_bounds__(256) void k_gemm(const float* __restrict__ om_w,
                                              const float* __restrict__ om_b,
                                              const float* __restrict__ gn_w,
                                              const float* __restrict__ gn_b) {
    __shared__ float sm[9344];   // union: As[16][132]+Bs[16][72] | Ep[128][73]
    float (*As)[132] = (float(*)[132])sm;
    float (*Bs)[72]  = (float(*)[72])(sm + 16 * 132);
    float (*Ep)[73]  = (float(*)[73])sm;

    const int tid = threadIdx.x;
    const int bm = blockIdx.x;
    const int by = blockIdx.y;
    const int mthr = tid & 31;
    const int nthr = tid >> 5;
    const int ob = by * 72 + nthr * 9;

    float acc[4][9];
    #pragma unroll
    for (int j = 0; j < 9; ++j) {
        float bb = om_b[ob + j];
        #pragma unroll
        for (int i = 0; i < 4; ++i) acc[i][j] = bb;
    }

    const int c0 = (tid & 3) * 4;
    const int rowb = tid >> 2;

    for (int kc = 0; kc < 8; ++kc) {
        // ---- load A (128 rows x 16 c), fused norm + exact GELU ----
        #pragma unroll
        for (int pass = 0; pass < 2; ++pass) {
            int row = pass * 64 + rowb;
            int p = bm * 128 + row;
            int n = p / HWSZ;
            float mu = g_mean[n], rs = g_rs[n];
            float4 xv = *(const float4*)&g_x1[(size_t)p * CC + kc * 16 + c0];
            float vv[4] = {xv.x, xv.y, xv.z, xv.w};
            #pragma unroll
            for (int j = 0; j < 4; ++j) {
                int c = kc * 16 + c0 + j;
                float v = (vv[j] - mu) * rs * gn_w[c] + gn_b[c];
                v = 0.5f * v * (1.0f + erff(v * 0.7071067811865475f));
                As[c0 + j][row] = v;
            }
        }
        // ---- load B (16 c x 72 o) ----
        for (int idx = tid; idx < 288; idx += 256) {
            int nn = idx >> 2;
            int cc0 = (idx & 3) * 4;
            float4 wv = *(const float4*)&om_w[(size_t)(by * 72 + nn) * CC + kc * 16 + cc0];
            Bs[cc0 + 0][nn] = wv.x;
            Bs[cc0 + 1][nn] = wv.y;
            Bs[cc0 + 2][nn] = wv.z;
            Bs[cc0 + 3][nn] = wv.w;
        }
        __syncthreads();
        #pragma unroll
        for (int kk = 0; kk < 16; ++kk) {
            float4 a4 = *(const float4*)&As[kk][mthr * 4];
            float a[4] = {a4.x, a4.y, a4.z, a4.w};
            float b[9];
            #pragma unroll
            for (int j = 0; j < 9; ++j) b[j] = Bs[kk][nthr * 9 + j];
            #pragma unroll
            for (int i = 0; i < 4; ++i)
                #pragma unroll
                for (int j = 0; j < 9; ++j)
                    acc[i][j] = fmaf(a[i], b[j], acc[i][j]);
        }
        __syncthreads();
    }

    // ---- epilogue: stage through smem, coalesced store ----
    #pragma unroll
    for (int i = 0; i < 4; ++i)
        #pragma unroll
        for (int j = 0; j < 9; ++j)
            Ep[mthr * 4 + i][nthr * 9 + j] = acc[i][j];
    __syncthreads();
    for (int idx = tid; idx < 9216; idx += 256) {
        int r = idx / 72;
        int col = idx - r * 72;
        int p = bm * 128 + r;
        g_om[(size_t)p * OMD + by * 72 + col] = Ep[r][col];
    }
}

// ---------------- K4: deformable bilinear sampling + NCHW output ----------------
// grid 1152, block 256. Block = 64 pixels; 4-lane group per (pixel, g), float4 channels.
__global__ __launch_bounds__(256) void k_sample(float* __restrict__ out) {
    __shared__ float tile[64][133];

    const int tid = threadIdx.x;
    const int gidx = tid >> 2;       // 0..63 pixel in block
    const int l = tid & 3;           // channel quad
    const int pb = blockIdx.x * 64;
    const int p = pb + gidx;
    const int n = p / HWSZ;
    const int rem = p - n * HWSZ;
    const int h = rem / WW;
    const int w = rem - h * WW;

    const float* xb = g_xnhwc + (size_t)n * HWSZ * CC;

    for (int g = 0; g < GG; ++g) {
        const float* omr = g_om + (size_t)p * OMD + g * 27;
        const int cbase = g * GCH + l * 4;
        float ax = 0.f, ay = 0.f, az = 0.f, aw = 0.f;
        #pragma unroll
        for (int k = 0; k < 9; ++k) {
            float offx = omr[2 * k];
            float offy = omr[2 * k + 1];
            float m    = omr[18 + k];
            float ly = (float)(h + (k / 3) - 1) + offy;
            float lx = (float)(w + (k % 3) - 1) + offx;
            float y0f = floorf(ly), x0f = floorf(lx);
            float fy = ly - y0f, fx = lx - x0f;
            int y0 = (int)y0f, x0 = (int)x0f;
            float w00 = (1.f - fy) * (1.f - fx) * m;
            float w01 = (1.f - fy) * fx * m;
            float w10 = fy * (1.f - fx) * m;
            float w11 = fy * fx * m;
            #pragma unroll
            for (int t = 0; t < 4; ++t) {
                int yy = y0 + (t >> 1);
                int xx = x0 + (t & 1);
                float wt = (t == 0) ? w00 : (t == 1) ? w01 : (t == 2) ? w10 : w11;
                if ((unsigned)yy < HH && (unsigned)xx < WW) {
                    const float4 v = *(const float4*)&xb[(size_t)((yy * WW + xx)) * CC + cbase];
                    ax = fmaf(wt, v.x, ax);
                    ay = fmaf(wt, v.y, ay);
                    az = fmaf(wt, v.z, az);
                    aw = fmaf(wt, v.w, aw);
                }
            }
        }
        tile[gidx][cbase + 0] = ax;
        tile[gidx][cbase + 1] = ay;
        tile[gidx][cbase + 2] = az;
        tile[gidx][cbase + 3] = aw;
    }
    __syncthreads();

    // coalesced NCHW writeout: 128 channels x 64 pixels
    const int hw0 = pb - n * HWSZ;
    float* ob = out + (size_t)n * CC * HWSZ;
    for (int idx = tid; idx < 8192; idx += 256) {
        int c = idx >> 6;
        int pp = idx & 63;
        ob[(size_t)c * HWSZ + hw0 + pp] = tile[pp][c];
    }
}

// ---------------- launcher ----------------
extern "C" void kernel_launch(void* const* d_in, const int* in_sizes, int n_in,
                              void* d_out, int out_size) {
    const float* x    = (const float*)d_in[0];
    const float* dw_w = (const float*)d_in[1];
    const float* dw_b = (const float*)d_in[2];
    const float* gn_w = (const float*)d_in[3];
    const float* gn_b = (const float*)d_in[4];
    const float* om_w = (const float*)d_in[5];
    const float* om_b = (const float*)d_in[6];
    float* out = (float*)d_out;

    k_init<<<1, 32>>>();
    dim3 g1(HH, CC / 32, NN), b1(96, 2);
    k_dwconv<<<g1, b1>>>(x, dw_w, dw_b);
    k_stats<<<1, 8>>>();
    dim3 g3(NHW / 128, 3);
    k_gemm<<<g3, 256>>>(om_w, om_b, gn_w, gn_b);
    k_sample<<<NHW / 64, 256>>>(out);
}

// round 2
// speedup vs baseline: 1.1602x; 1.1602x over previous
#include <cuda_runtime.h>
#include <math.h>

#define NN 8
#define CC 128
#define HH 96
#define WW 96
#define GG 8
#define GCH 16
#define HWSZ (HH*WW)            // 9216
#define NHW (NN*HWSZ)           // 73728
#define OMD 216
#define BNP 224                 // padded N for the GEMM
#define GN_EPS 1e-5f

// ---------------- device scratch ----------------
__device__ float g_x1[NHW * CC];      // dwconv+bias output, NHWC
__device__ float g_xnhwc[NHW * CC];   // input transposed to NHWC
__device__ float g_om[NHW * OMD];     // offsets/masks GEMM output
__device__ float g_omwT[CC * BNP];    // om_w transposed [k][n], zero-padded
__device__ float g_ombp[BNP];         // om_b zero-padded
__device__ float g_sum[NN];
__device__ float g_sumsq[NN];
__device__ float g_mean[NN];
__device__ float g_rs[NN];

// ---------------- f32x2 helpers ----------------
__device__ __forceinline__ unsigned long long pack2(float lo, float hi) {
    unsigned long long d;
    asm("mov.b64 %0, {%1, %2};" : "=l"(d) : "f"(lo), "f"(hi));
    return d;
}
__device__ __forceinline__ void unpack2(unsigned long long v, float& lo, float& hi) {
    asm("mov.b64 {%0, %1}, %2;" : "=f"(lo), "=f"(hi) : "l"(v));
}
__device__ __forceinline__ void fma2(unsigned long long& acc, unsigned long long a,
                                     unsigned long long b) {
    asm("fma.rn.f32x2 %0, %1, %2, %0;" : "+l"(acc) : "l"(a), "l"(b));
}

// ---------------- K0: init stats + transpose om_w ----------------
__global__ void k_init() {
    int i = threadIdx.x;
    if (i < NN) { g_sum[i] = 0.f; g_sumsq[i] = 0.f; }
}

__global__ __launch_bounds__(256) void k_prep(const float* __restrict__ om_w,
                                              const float* __restrict__ om_b) {
    int idx = blockIdx.x * 256 + threadIdx.x;
    if (idx < CC * BNP) {
        int k = idx / BNP;
        int n = idx - k * BNP;
        g_omwT[idx] = (n < OMD) ? om_w[n * CC + k] : 0.f;
    }
    if (idx < BNP) g_ombp[idx] = (idx < OMD) ? om_b[idx] : 0.f;
}

// ---------------- K1: depthwise conv + bias, NHWC transpose, stats ----------------
// grid (H, C/32, N), block (96, 2)
__global__ __launch_bounds__(192) void k_dwconv(const float* __restrict__ x,
                                                const float* __restrict__ dw_w,
                                                const float* __restrict__ dw_b) {
    int h  = blockIdx.x;
    int cb = blockIdx.y;
    int n  = blockIdx.z;
    int w  = threadIdx.x;
    int ty = threadIdx.y;
    int tid = ty * 96 + w;

    __shared__ float s_out[32][97];
    __shared__ float s_in[32][97];
    __shared__ float rbuf[12];

    float s1 = 0.f, s2 = 0.f;

    #pragma unroll 4
    for (int i = 0; i < 16; ++i) {
        int c = cb * 32 + ty * 16 + i;
        const float* xc = x + ((size_t)(n * CC + c)) * HWSZ;
        float wgt[9];
        #pragma unroll
        for (int t = 0; t < 9; ++t) wgt[t] = dw_w[c * 9 + t];
        float acc = dw_b[c];
        float ctr = 0.f;
        #pragma unroll
        for (int dy = -1; dy <= 1; ++dy) {
            int y = h + dy;
            if ((unsigned)y < HH) {
                #pragma unroll
                for (int dx = -1; dx <= 1; ++dx) {
                    int xx = w + dx;
                    if ((unsigned)xx < WW) {
                        float v = xc[y * WW + xx];
                        acc += v * wgt[(dy + 1) * 3 + (dx + 1)];
                        if (dy == 0 && dx == 0) ctr = v;
                    }
                }
            }
        }
        s_out[ty * 16 + i][w] = acc;
        s_in [ty * 16 + i][w] = ctr;
        s1 += acc;
        s2 += acc * acc;
    }

    #pragma unroll
    for (int o = 16; o; o >>= 1) {
        s1 += __shfl_down_sync(0xffffffffu, s1, o);
        s2 += __shfl_down_sync(0xffffffffu, s2, o);
    }
    int wid = tid >> 5, lane = tid & 31;
    if (lane == 0) { rbuf[wid] = s1; rbuf[6 + wid] = s2; }
    __syncthreads();
    if (tid == 0) {
        float a = 0.f, b = 0.f;
        #pragma unroll
        for (int i = 0; i < 6; ++i) { a += rbuf[i]; b += rbuf[6 + i]; }
        atomicAdd(&g_sum[n], a);
        atomicAdd(&g_sumsq[n], b);
    }

    size_t base = ((size_t)(n * HWSZ + h * WW)) * CC + cb * 32;
    for (int idx = tid; idx < 3072; idx += 192) {
        int ww = idx >> 5;
        int cc = idx & 31;
        g_x1  [base + (size_t)ww * CC + cc] = s_out[cc][ww];
        g_xnhwc[base + (size_t)ww * CC + cc] = s_in[cc][ww];
    }
}

// ---------------- K2: finalize stats ----------------
__global__ void k_stats() {
    int i = threadIdx.x;
    if (i < NN) {
        const float inv = 1.f / (float)(CC * HWSZ);
        float mu  = g_sum[i] * inv;
        float var = g_sumsq[i] * inv - mu * mu;
        g_mean[i] = mu;
        g_rs[i]   = rsqrtf(var + GN_EPS);
    }
}

// ---------------- K3: fused norm+GELU + GEMM via fma.rn.f32x2 ----------------
// grid 576, block 256. BM=128, full N (216 pad 224) per block, all of B in smem.
// Thread tile: 4 rows x 28 cols = 56 packed f32x2 accumulators.
extern __shared__ float sm_g[];
__global__ __launch_bounds__(256, 1) void k_gemm(const float* __restrict__ gn_w,
                                                 const float* __restrict__ gn_b) {
    float* Bs = sm_g;                 // [128][BNP]
    float* As = sm_g + CC * BNP;      // [16][128]

    const int tid = threadIdx.x;
    const int bm  = blockIdx.x;
    const int tm  = tid & 31;         // 32 m-groups of 4 rows
    const int tn  = tid >> 5;         // 8 n-groups of 28 cols

    // stage all of B^T into smem (coalesced float4, conflict-free)
    {
        const float4* src = (const float4*)g_omwT;
        float4* dst = (float4*)Bs;
        #pragma unroll
        for (int i = 0; i < CC * BNP / 4 / 256; ++i)
            dst[i * 256 + tid] = src[i * 256 + tid];
    }

    // init accumulators from bias
    unsigned long long acc[4][14];
    #pragma unroll
    for (int j = 0; j < 14; ++j) {
        unsigned long long bb = pack2(g_ombp[tn * 28 + 2 * j], g_ombp[tn * 28 + 2 * j + 1]);
        #pragma unroll
        for (int i = 0; i < 4; ++i) acc[i][j] = bb;
    }

    const int c0 = (tid & 3) * 4;
    const int rowb = tid >> 2;

    for (int kc = 0; kc < 8; ++kc) {
        // ---- load A chunk (128 rows x 16 k), fused norm + exact GELU ----
        #pragma unroll
        for (int pass = 0; pass < 2; ++pass) {
            int row = pass * 64 + rowb;
            int p = bm * 128 + row;
            int n = p / HWSZ;
            float mu = g_mean[n], rs = g_rs[n];
            float4 xv = *(const float4*)&g_x1[(size_t)p * CC + kc * 16 + c0];
            float vv[4] = {xv.x, xv.y, xv.z, xv.w};
            #pragma unroll
            for (int j = 0; j < 4; ++j) {
                int c = kc * 16 + c0 + j;
                float v = (vv[j] - mu) * rs * gn_w[c] + gn_b[c];
                v = 0.5f * v * (1.0f + erff(v * 0.7071067811865475f));
                As[(c0 + j) * 128 + row] = v;
            }
        }
        __syncthreads();
        #pragma unroll
        for (int kk = 0; kk < 16; ++kk) {
            float4 a4 = *(const float4*)&As[kk * 128 + tm * 4];
            unsigned long long a2[4];
            a2[0] = pack2(a4.x, a4.x);
            a2[1] = pack2(a4.y, a4.y);
            a2[2] = pack2(a4.z, a4.z);
            a2[3] = pack2(a4.w, a4.w);
            const unsigned long long* brow =
                (const unsigned long long*)&Bs[(kc * 16 + kk) * BNP + tn * 28];
            #pragma unroll
            for (int j = 0; j < 14; ++j) {
                unsigned long long b2 = brow[j];   // two adjacent B floats = f32x2
                fma2(acc[0][j], a2[0], b2);
                fma2(acc[1][j], a2[1], b2);
                fma2(acc[2][j], a2[2], b2);
                fma2(acc[3][j], a2[3], b2);
            }
        }
        __syncthreads();
    }

    // ---- epilogue: reuse smem as Ep[128][227], coalesced store ----
    float* Ep = sm_g;
    #pragma unroll
    for (int i = 0; i < 4; ++i) {
        int row = tm * 4 + i;
        #pragma unroll
        for (int j = 0; j < 14; ++j) {
            float lo, hi;
            unpack2(acc[i][j], lo, hi);
            Ep[row * 227 + tn * 28 + 2 * j]     = lo;
            Ep[row * 227 + tn * 28 + 2 * j + 1] = hi;
        }
    }
    __syncthreads();
    for (int idx = tid; idx < 128 * OMD; idx += 256) {
        int r = idx / OMD;
        int col = idx - r * OMD;
        g_om[(size_t)(bm * 128 + r) * OMD + col] = Ep[r * 227 + col];
    }
}

// ---------------- K4: deformable bilinear sampling + NCHW output ----------------
// grid 1152, block 256. Block = 64 pixels; om tile staged through smem.
extern __shared__ float sm_s[];
__global__ __launch_bounds__(256) void k_sample(float* __restrict__ out) {
    float* s_om = sm_s;                      // [64][220]
    float (*tile)[133] = (float(*)[133])(sm_s + 64 * 220);

    const int tid = threadIdx.x;
    const int gidx = tid >> 2;       // 0..63 pixel in block
    const int l = tid & 3;           // channel quad
    const int pb = blockIdx.x * 64;
    const int p = pb + gidx;
    const int n = p / HWSZ;
    const int rem = p - n * HWSZ;
    const int h = rem / WW;
    const int w = rem - h * WW;

    // stage om tile: 64 pixels x 216 floats, coalesced float4
    {
        const float4* src = (const float4*)(g_om + (size_t)pb * OMD);
        for (int idx = tid; idx < 64 * 54; idx += 256) {
            int pix = idx / 54;
            int c4 = idx - pix * 54;
            float4 v = src[pix * 54 + c4];
            *(float4*)&s_om[pix * 220 + c4 * 4] = v;
        }
    }
    __syncthreads();

    const float* xb = g_xnhwc + (size_t)n * HWSZ * CC;
    const float* omr0 = &s_om[gidx * 220];

    for (int g = 0; g < GG; ++g) {
        const float* omr = omr0 + g * 27;
        const int cbase = g * GCH + l * 4;
        float ax = 0.f, ay = 0.f, az = 0.f, aw = 0.f;
        #pragma unroll
        for (int k = 0; k < 9; ++k) {
            float offx = omr[2 * k];
            float offy = omr[2 * k + 1];
            float m    = omr[18 + k];
            float ly = (float)(h + (k / 3) - 1) + offy;
            float lx = (float)(w + (k % 3) - 1) + offx;
            float y0f = floorf(ly), x0f = floorf(lx);
            float fy = ly - y0f, fx = lx - x0f;
            int y0 = (int)y0f, x0 = (int)x0f;
            float w00 = (1.f - fy) * (1.f - fx) * m;
            float w01 = (1.f - fy) * fx * m;
            float w10 = fy * (1.f - fx) * m;
            float w11 = fy * fx * m;
            #pragma unroll
            for (int t = 0; t < 4; ++t) {
                int yy = y0 + (t >> 1);
                int xx = x0 + (t & 1);
                float wt = (t == 0) ? w00 : (t == 1) ? w01 : (t == 2) ? w10 : w11;
                if ((unsigned)yy < HH && (unsigned)xx < WW) {
                    const float4 v = *(const float4*)&xb[(size_t)((yy * WW + xx)) * CC + cbase];
                    ax = fmaf(wt, v.x, ax);
                    ay = fmaf(wt, v.y, ay);
                    az = fmaf(wt, v.z, az);
                    aw = fmaf(wt, v.w, aw);
                }
            }
        }
        tile[gidx][cbase + 0] = ax;
        tile[gidx][cbase + 1] = ay;
        tile[gidx][cbase + 2] = az;
        tile[gidx][cbase + 3] = aw;
    }
    __syncthreads();

    const int hw0 = pb - n * HWSZ;
    float* ob = out + (size_t)n * CC * HWSZ;
    for (int idx = tid; idx < 8192; idx += 256) {
        int c = idx >> 6;
        int pp = idx & 63;
        ob[(size_t)c * HWSZ + hw0 + pp] = tile[pp][c];
    }
}

// ---------------- launcher ----------------
extern "C" void kernel_launch(void* const* d_in, const int* in_sizes, int n_in,
                              void* d_out, int out_size) {
    const float* x    = (const float*)d_in[0];
    const float* dw_w = (const float*)d_in[1];
    const float* dw_b = (const float*)d_in[2];
    const float* gn_w = (const float*)d_in[3];
    const float* gn_b = (const float*)d_in[4];
    const float* om_w = (const float*)d_in[5];
    const float* om_b = (const float*)d_in[6];
    float* out = (float*)d_out;

    const int smem_gemm = (CC * BNP + 16 * CC) * sizeof(float);    // 122880
    const int smem_samp = (64 * 220 + 64 * 133) * sizeof(float);   // 90368
    cudaFuncSetAttribute(k_gemm, cudaFuncAttributeMaxDynamicSharedMemorySize, smem_gemm);
    cudaFuncSetAttribute(k_sample, cudaFuncAttributeMaxDynamicSharedMemorySize, smem_samp);

    k_init<<<1, 32>>>();
    k_prep<<<(CC * BNP + 255) / 256, 256>>>(om_w, om_b);
    dim3 g1(HH, CC / 32, NN), b1(96, 2);
    k_dwconv<<<g1, b1>>>(x, dw_w, dw_b);
    k_stats<<<1, 8>>>();
    k_gemm<<<NHW / 128, 256, smem_gemm>>>(gn_w, gn_b);
    k_sample<<<NHW / 64, 256, smem_samp>>>(out);
}